// round 15
// baseline (speedup 1.0000x reference)
#include <cuda_runtime.h>
#include <cuda_bf16.h>
#include <cuda_fp16.h>
#include <math.h>
#include <stdint.h>

// Problem constants
#define B_  64
#define L_  196
#define F_  512
#define T_  32
#define H_  512
#define D_  512
#define V_  32000
#define G4_ 2048
#define M_ENC (B_*L_)          // 12544
#define M_FC  (T_*B_)          // 2048
#define KC_ 1536               // D+F+H
#define GRID_P 128

// ====================== warp-mma helpers (sm_80 baseline ISA) ==============
__device__ __forceinline__ uint32_t smem_to_u32(const void* p) {
    uint32_t a;
    asm("{ .reg .u64 t; cvta.to.shared.u64 t, %1; cvt.u32.u64 %0, t; }" : "=r"(a) : "l"(p));
    return a;
}

#define LDMX4(r0,r1,r2,r3,addr) \
    asm volatile("ldmatrix.sync.aligned.m8n8.x4.shared.b16 {%0,%1,%2,%3}, [%4];" \
        : "=r"(r0),"=r"(r1),"=r"(r2),"=r"(r3) : "r"(addr))

#define CP16(dst, src) \
    asm volatile("cp.async.cg.shared.global [%0], [%1], 16;" :: "r"(dst), "l"(src))
#define CP_COMMIT() asm volatile("cp.async.commit_group;")
#define CP_WAIT(n)  asm volatile("cp.async.wait_group %0;" :: "n"(n))

__device__ __forceinline__ void mma_bf16(float* c, const uint32_t* a, const uint32_t* b) {
    asm volatile(
        "mma.sync.aligned.m16n8k16.row.col.f32.bf16.bf16.f32 "
        "{%0,%1,%2,%3}, {%4,%5,%6,%7}, {%8,%9}, {%0,%1,%2,%3};"
        : "+f"(c[0]), "+f"(c[1]), "+f"(c[2]), "+f"(c[3])
        : "r"(a[0]), "r"(a[1]), "r"(a[2]), "r"(a[3]), "r"(b[0]), "r"(b[1]));
}
__device__ __forceinline__ void mma_f16(float* c, const uint32_t* a, const uint32_t* b) {
    asm volatile(
        "mma.sync.aligned.m16n8k16.row.col.f32.f16.f16.f32 "
        "{%0,%1,%2,%3}, {%4,%5,%6,%7}, {%8,%9}, {%0,%1,%2,%3};"
        : "+f"(c[0]), "+f"(c[1]), "+f"(c[2]), "+f"(c[3])
        : "r"(a[0]), "r"(a[1]), "r"(a[2]), "r"(a[3]), "r"(b[0]), "r"(b[1]));
}

__device__ __forceinline__ float ftanh(float x) {
    float y;
    asm("tanh.approx.f32 %0, %1;" : "=f"(y) : "f"(x));
    return y;
}

// ---------------- scratch (static device globals; no allocations) ----------
__device__ float g_encproj[M_ENC * H_];
__device__ __half g_encproj_h[M_ENC * H_];
__device__ float g_h[B_ * H_];
__device__ float g_c[B_ * H_];
__device__ float g_dec[B_ * H_];
// bf16 operands (gates path)
__device__ __nv_bfloat16 g_embh[T_ * B_ * D_];
__device__ __nv_bfloat16 g_embl[T_ * B_ * D_];
__device__ __nv_bfloat16 g_ctxh[B_ * F_];
__device__ __nv_bfloat16 g_ctxl[B_ * F_];
__device__ __nv_bfloat16 g_hh[B_ * H_];
__device__ __nv_bfloat16 g_hl[B_ * H_];
__device__ __nv_bfloat16 g_Wc_hi[(size_t)G4_ * KC_];
__device__ __nv_bfloat16 g_Wc_lo[(size_t)G4_ * KC_];
// fp16 operands (big GEMMs)
__device__ __half g_enc_h[M_ENC * F_];
__device__ __half g_We_h[H_ * F_];
__device__ __half g_We_l[H_ * F_];
__device__ __half g_Wf_h[(size_t)V_ * H_];
__device__ __half g_Hall_h[M_FC * H_];
__device__ unsigned g_barArr = 0;

__device__ __forceinline__ void gridbar() {
    __syncthreads();
    if (threadIdx.x == 0) {
        unsigned my;
        asm volatile("atom.global.release.gpu.add.u32 %0, [%1], 1;"
                     : "=r"(my) : "l"(&g_barArr) : "memory");
        my += 1u;
        unsigned target = ((my + GRID_P - 1u) / GRID_P) * GRID_P;
        for (;;) {
            unsigned v;
            asm volatile("ld.global.acquire.gpu.u32 %0, [%1];"
                         : "=r"(v) : "l"(&g_barArr) : "memory");
            if (v >= target) break;
            __nanosleep(128);
        }
    }
    __syncthreads();
}

// ---------------- fused preamble splits (float4 vectorized) ----------------
#define Q0 ((size_t)(M_ENC * F_) / 4)         // enc  -> fp16 single
#define Q1 ((size_t)(H_ * F_) / 4)            // We   -> fp16 hi/lo
#define Q2 (((size_t)V_ * H_) / 4)            // Wf   -> fp16 single
#define Q3 (((size_t)G4_ * KC_) / 4)          // Wc   -> bf16 hi/lo
#define QALL (Q0 + Q1 + Q2 + Q3)

__device__ __forceinline__ void st_h4(__half* p, size_t off, float4 v) {
    __half2* q = (__half2*)(p + off);
    q[0] = __floats2half2_rn(v.x, v.y);
    q[1] = __floats2half2_rn(v.z, v.w);
}
__device__ __forceinline__ void st_h4_dual(__half* ph, __half* pl, size_t off, float4 v) {
    __half hx = __float2half_rn(v.x), hy = __float2half_rn(v.y);
    __half hz = __float2half_rn(v.z), hw = __float2half_rn(v.w);
    __half2* qh = (__half2*)(ph + off);
    qh[0] = __halves2half2(hx, hy); qh[1] = __halves2half2(hz, hw);
    __half2* ql = (__half2*)(pl + off);
    ql[0] = __floats2half2_rn(v.x - __half2float(hx), v.y - __half2float(hy));
    ql[1] = __floats2half2_rn(v.z - __half2float(hz), v.w - __half2float(hw));
}
__device__ __forceinline__ void st_b4_dual(__nv_bfloat16* ph, __nv_bfloat16* pl,
                                           size_t off, float4 v) {
    __nv_bfloat16 hx = __float2bfloat16(v.x), hy = __float2bfloat16(v.y);
    __nv_bfloat16 hz = __float2bfloat16(v.z), hw = __float2bfloat16(v.w);
    __nv_bfloat162* qh = (__nv_bfloat162*)(ph + off);
    qh[0] = __nv_bfloat162{hx, hy}; qh[1] = __nv_bfloat162{hz, hw};
    __nv_bfloat162* ql = (__nv_bfloat162*)(pl + off);
    ql[0] = __nv_bfloat162{__float2bfloat16(v.x - __bfloat162float(hx)),
                           __float2bfloat16(v.y - __bfloat162float(hy))};
    ql[1] = __nv_bfloat162{__float2bfloat16(v.z - __bfloat162float(hz)),
                           __float2bfloat16(v.w - __bfloat162float(hw))};
}

__global__ void k_prep(const float* __restrict__ enc, const float* __restrict__ We,
                       const float* __restrict__ Wf, const float* __restrict__ W_ih,
                       const float* __restrict__ W_hh) {
    size_t i4 = (size_t)blockIdx.x * 256 + threadIdx.x;   // exact grid
    if (i4 < Q0) {
        float4 v = ((const float4*)enc)[i4];
        st_h4(g_enc_h, i4 * 4, v);
    } else if (i4 < Q0 + Q1) {
        size_t o = i4 - Q0;
        float4 v = ((const float4*)We)[o];
        st_h4_dual(g_We_h, g_We_l, o * 4, v);
    } else if (i4 < Q0 + Q1 + Q2) {
        size_t o = i4 - Q0 - Q1;
        float4 v = ((const float4*)Wf)[o];
        st_h4(g_Wf_h, o * 4, v);
    } else {
        size_t o = i4 - Q0 - Q1 - Q2;
        size_t off = o * 4;
        int m = (int)(off / KC_), k = (int)(off % KC_);
        float4 v = (k < 1024)
            ? *(const float4*)(W_ih + (size_t)m * 1024 + k)
            : *(const float4*)(W_hh + (size_t)m * 512 + (k - 1024));
        st_b4_dual(g_Wc_hi, g_Wc_lo, off, v);
    }
}

// ---------------- convert encproj fp32 -> fp16 (coalesced) ------------------
__global__ void k_conv(const float* __restrict__ src) {
    size_t i4 = (size_t)blockIdx.x * 256 + threadIdx.x;   // over float4, exact
    float4 v = ((const float4*)src)[i4];
    st_h4(g_encproj_h, i4 * 4, v);
}

// ---------------- init: zero state, gather embeddings -> bf16 hi/lo --------
__global__ void k_init(const int* __restrict__ captions,
                       const float* __restrict__ embedding) {
    int idx = blockIdx.x * 256 + threadIdx.x;      // T*B*D exact
    if (idx < B_ * H_) {
        g_h[idx] = 0.f; g_c[idx] = 0.f;
        g_hh[idx] = __float2bfloat16(0.f);
        g_hl[idx] = __float2bfloat16(0.f);
    }
    int t   = idx >> 15;
    int rem = idx & 32767;
    int b   = rem >> 9;
    int d   = rem & 511;
    int cap = captions[b * T_ + t];
    float x = embedding[(size_t)cap * D_ + d];
    __nv_bfloat16 h = __float2bfloat16(x);
    g_embh[idx] = h;
    g_embl[idx] = __float2bfloat16(x - __bfloat162float(h));
}

// ---------------- ctx0 = mean over L -> bf16 hi/lo -------------------------
__global__ void k_ctx0(const float* __restrict__ enc) {
    int idx = blockIdx.x * 256 + threadIdx.x;      // B*F exact
    int b = idx >> 9, f = idx & 511;
    const float* p = enc + ((size_t)b * L_) * F_ + f;
    float s = 0.f;
    for (int l = 0; l < L_; ++l) s += p[(size_t)l * F_];
    s *= (1.0f / (float)L_);
    __nv_bfloat16 h = __float2bfloat16(s);
    g_ctxh[idx] = h;
    g_ctxl[idx] = __float2bfloat16(s - __bfloat162float(h));
}

// ---------------- big GEMM: CTA 128x128, warp tile 64x64, 128 threads ------
#define T32  (128 * 40)
#define T32B (T32 * 2)                  // 10240 bytes per tile
#define PIPE_SMEM_2P (3 * 3 * T32B)     // two-pass: 3 stages x 3 tiles = 92160
#define PIPE_SMEM_1P (3 * 2 * T32B)     // one-pass: 3 stages x 2 tiles = 61440

__global__ __launch_bounds__(128, 2) void k_mma128(
    const __half* __restrict__ A,
    const __half* __restrict__ Bhi, const __half* __restrict__ Blo,
    const float* __restrict__ bias, float* __restrict__ out,
    int K, int ldc, int fc_remap, int two_pass)
{
    extern __shared__ char smem[];
    uint32_t sb = smem_to_u32(smem);
    int tid = threadIdx.x, wid = tid >> 5, lane = tid & 31;
    int m0 = blockIdx.x * 128, n0 = blockIdx.y * 128;
    int warp_m = wid & 1, warp_n = wid >> 1;   // 2 x 2 warp grid, warp tile 64x64
    uint32_t stg = (uint32_t)((two_pass ? 3 : 2) * T32B);

    float acc[4][8][4];
#pragma unroll
    for (int i = 0; i < 4; i++)
#pragma unroll
        for (int j = 0; j < 8; j++)
#pragma unroll
            for (int r = 0; r < 4; r++) acc[i][j][r] = 0.f;

    uint32_t so_ld = (uint32_t)(tid * 80);          // one 80-byte row per thread
    int sub = lane >> 3, ri = lane & 7;
    uint32_t aoff = (uint32_t)((((sub & 1) * 8 + ri) * 40 + (sub >> 1) * 8) * 2)
                  + (uint32_t)(warp_m * 64 * 80);
    uint32_t boff = (uint32_t)((((sub >> 1) * 8 + ri) * 40 + (sub & 1) * 8) * 2)
                  + (uint32_t)(warp_n * 64 * 80);

    int NC = K >> 5;

#define ISSUE(c, s) do { \
        int k0 = (c) << 5; \
        uint32_t st = sb + (uint32_t)(s) * stg; \
        size_t gA = (size_t)(m0 + tid) * K + k0; \
        size_t gB = (size_t)(n0 + tid) * K + k0; \
        _Pragma("unroll") \
        for (int q = 0; q < 4; ++q) { \
            CP16(st + so_ld + q * 16, A + gA + q * 8); \
            CP16(st + 1 * T32B + so_ld + q * 16, Bhi + gB + q * 8); \
            if (two_pass) CP16(st + 2 * T32B + so_ld + q * 16, Blo + gB + q * 8); \
        } \
        CP_COMMIT(); \
    } while (0)

    ISSUE(0, 0);
    ISSUE(1, 1);
    for (int c = 0; c < NC; ++c) {
        if (c + 1 < NC) CP_WAIT(1); else CP_WAIT(0);
        __syncthreads();
        if (c + 2 < NC) ISSUE(c + 2, (c + 2) % 3);
        int s = c % 3;
        uint32_t bA  = sb + (uint32_t)s * stg + aoff;
        uint32_t bBh = sb + (uint32_t)s * stg + 1 * T32B + boff;
        uint32_t bBl = sb + (uint32_t)s * stg + 2 * T32B + boff;
#pragma unroll
        for (int ks = 0; ks < 32; ks += 16) {
            uint32_t ah[4][4], bh[8][2];
#pragma unroll
            for (int mi = 0; mi < 4; ++mi)
                LDMX4(ah[mi][0], ah[mi][1], ah[mi][2], ah[mi][3],
                      bA + (uint32_t)(mi * 16 * 80 + ks * 2));
#pragma unroll
            for (int j = 0; j < 4; ++j)
                LDMX4(bh[2 * j][0], bh[2 * j][1], bh[2 * j + 1][0], bh[2 * j + 1][1],
                      bBh + (uint32_t)(j * 16 * 80 + ks * 2));
#pragma unroll
            for (int mi = 0; mi < 4; ++mi)
#pragma unroll
                for (int ni = 0; ni < 8; ++ni)
                    mma_f16(acc[mi][ni], ah[mi], bh[ni]);
            if (two_pass) {
                uint32_t bl[8][2];
#pragma unroll
                for (int j = 0; j < 4; ++j)
                    LDMX4(bl[2 * j][0], bl[2 * j][1], bl[2 * j + 1][0], bl[2 * j + 1][1],
                          bBl + (uint32_t)(j * 16 * 80 + ks * 2));
#pragma unroll
                for (int mi = 0; mi < 4; ++mi)
#pragma unroll
                    for (int ni = 0; ni < 8; ++ni)
                        mma_f16(acc[mi][ni], ah[mi], bl[ni]);
            }
        }
    }
#undef ISSUE

    int g = lane >> 2, t4 = lane & 3;
    float2 bv[8];
#pragma unroll
    for (int ni = 0; ni < 8; ++ni)
        bv[ni] = *(const float2*)(bias + n0 + warp_n * 64 + ni * 8 + 2 * t4);
#pragma unroll
    for (int mi = 0; mi < 4; ++mi)
#pragma unroll
        for (int rr = 0; rr < 2; ++rr) {
            int m = m0 + warp_m * 64 + mi * 16 + rr * 8 + g;
            int row = fc_remap ? ((m & 63) * T_ + (m >> 6)) : m;
            float* po = out + (size_t)row * ldc + n0 + warp_n * 64 + 2 * t4;
#pragma unroll
            for (int ni = 0; ni < 8; ++ni) {
                float2 v;
                v.x = acc[mi][ni][rr * 2 + 0] + bv[ni].x;
                v.y = acc[mi][ni][rr * 2 + 1] + bv[ni].y;
                *(float2*)(po + ni * 8) = v;
            }
        }
}

// ---------------- persistent fused recurrence kernel (512 threads) ---------
// dyn smem layout (bytes):
//   gates: stage s at s*23040 (3 stages = 69120); gatebuf @69120 (16384)
//          -> 85504 max
//   dec:   hs[64][65]@0 (16640), ws[4][64]@16640 (1024), pr[512]@17664 (2048)
//   attn:  dec_s[512]@0, vw_s[512]@2048, sc[200]@4096, sred[256]@5120,
//          red2[16][256]@6144 (16384) -> 22528
#define GB_OFF 69120
#define LOOP_SMEM 85504

__global__ __launch_bounds__(512, 1) void k_loop(
    const float* __restrict__ enc, const float* __restrict__ Wd,
    const float* __restrict__ bd, const float* __restrict__ vw,
    const float* __restrict__ vb, const float* __restrict__ b_ih,
    const float* __restrict__ b_hh)
{
    extern __shared__ char smL[];
    uint32_t sb = smem_to_u32(smL);
    int cta = blockIdx.x;
    int tid = threadIdx.x, wid = tid >> 5, lane = tid & 31;
    int sub = lane >> 3, ri = lane & 7;

    // fused-gates constants: 16 warps = kq(4 K-quarters) x ng(4 batch groups)
    int kq = wid >> 2, ng = wid & 3;
    uint32_t aoffG = (uint32_t)((((sub & 1) * 8 + ri) * 72 + (sub >> 1) * 8) * 2);
    uint32_t boffG = (uint32_t)((((sub >> 1) * 8 + ri) * 72 + (sub & 1) * 8) * 2)
                   + (uint32_t)(ng * 16 * 144);
    uint32_t ksb = (uint32_t)(kq * 32);            // byte offset of this warp's 16-col slice

    for (int t = 0; t < T_; ++t) {
        if (t > 0) {
            // ---- dec: cta computes dec[:, cta*4 .. +3]; 2 threads/output ----
            {
                float* hs = (float*)smL;                // [64][65]
                float* ws = (float*)(smL + 16640);      // [4][64]
                float* pr = (float*)(smL + 17664);      // [512]
                int n0 = cta * 4;
                int bq = tid & 63, jj = (tid >> 6) & 3, kh = tid >> 8;
                float acc = 0.f;
                for (int kb = 0; kb < 512; kb += 64) {
#pragma unroll
                    for (int it = 0; it < 2; ++it) {
                        int u = tid + it * 512;         // 0..1023 float4 slots
                        int r = u >> 4, kk = (u & 15) * 4;
                        float4 v = *(const float4*)(g_h + (size_t)r * 512 + kb + kk);
                        hs[r * 65 + kk + 0] = v.x; hs[r * 65 + kk + 1] = v.y;
                        hs[r * 65 + kk + 2] = v.z; hs[r * 65 + kk + 3] = v.w;
                    }
                    if (tid < 64) {
                        int n = tid >> 4, kk = (tid & 15) * 4;
                        float4 v = *(const float4*)(Wd + (size_t)(n0 + n) * 512 + kb + kk);
                        ws[n * 64 + kk + 0] = v.x; ws[n * 64 + kk + 1] = v.y;
                        ws[n * 64 + kk + 2] = v.z; ws[n * 64 + kk + 3] = v.w;
                    }
                    __syncthreads();
#pragma unroll
                    for (int k = 0; k < 32; ++k)
                        acc += hs[bq * 65 + kh * 32 + k] * ws[jj * 64 + kh * 32 + k];
                    __syncthreads();
                }
                pr[tid] = acc;
                __syncthreads();
                if (tid < 256)
                    g_dec[(size_t)bq * 512 + n0 + jj] = pr[tid] + pr[tid + 256] + bd[n0 + jj];
            }
            gridbar();

            // ---- merged attention: b = cta>>1, f-half = cta&1 ----
            {
                float* dec_s = (float*)smL;             // [512]
                float* vw_s  = (float*)(smL + 2048);    // [512]
                float* sc    = (float*)(smL + 4096);    // [200]
                float* sred  = (float*)(smL + 5120);    // [256]
                float* red2  = (float*)(smL + 6144);    // [16][256]
                int b = cta >> 1, f0 = (cta & 1) * 256;
                dec_s[tid] = g_dec[(size_t)b * 512 + tid];
                vw_s[tid]  = vw[tid];
                __syncthreads();
                const float2* dec2 = (const float2*)dec_s;
                const float2* vw2  = (const float2*)vw_s;
                float v_b = vb[0];
                for (int l = wid; l < L_; l += 16) {
                    const __half2* ep2 = (const __half2*)(g_encproj_h + ((size_t)(b * L_ + l)) * 512);
                    float s = 0.f;
#pragma unroll
                    for (int j = 0; j < 8; ++j) {
                        int idx = lane + 32 * j;
                        float2 e = __half22float2(ep2[idx]);
                        float2 dd = dec2[idx];
                        float2 vv = vw2[idx];
                        s += ftanh(e.x + dd.x) * vv.x + ftanh(e.y + dd.y) * vv.y;
                    }
#pragma unroll
                    for (int off = 16; off; off >>= 1) s += __shfl_xor_sync(0xffffffffu, s, off);
                    if (lane == 0) sc[l] = s + v_b;
                }
                __syncthreads();
                if (tid < 256) {
                    float mv = (tid < L_) ? sc[tid] : -1e30f;
                    sred[tid] = mv;
                }
                __syncthreads();
                for (int s = 128; s; s >>= 1) {
                    if (tid < s) sred[tid] = fmaxf(sred[tid], sred[tid + s]);
                    __syncthreads();
                }
                float mx = sred[0]; __syncthreads();
                float ev = 0.f;
                if (tid < 256) {
                    ev = (tid < L_) ? __expf(sc[tid] - mx) : 0.f;
                    sred[tid] = ev;
                }
                __syncthreads();
                for (int s = 128; s; s >>= 1) {
                    if (tid < s) sred[tid] += sred[tid + s];
                    __syncthreads();
                }
                float inv = 1.0f / sred[0]; __syncthreads();
                if (tid < L_) sc[tid] = ev * inv;
                __syncthreads();
                float2 a2[4];
#pragma unroll
                for (int j = 0; j < 4; ++j) a2[j] = float2{0.f, 0.f};
                for (int l = wid; l < L_; l += 16) {
                    float s = sc[l];
                    const __half2* e2 = (const __half2*)(g_enc_h + ((size_t)(b * L_ + l)) * 512 + f0);
#pragma unroll
                    for (int j = 0; j < 4; ++j) {
                        float2 e = __half22float2(e2[lane + 32 * j]);
                        a2[j].x += s * e.x; a2[j].y += s * e.y;
                    }
                }
#pragma unroll
                for (int j = 0; j < 4; ++j)
                    ((float2*)(red2 + wid * 256))[lane + 32 * j] = a2[j];
                __syncthreads();
                if (tid < 256) {
                    float a0 = 0.f;
#pragma unroll
                    for (int w = 0; w < 16; w++) a0 += red2[w * 256 + tid];
                    int fi = b * 512 + f0 + tid;
                    __nv_bfloat16 h = __float2bfloat16(a0);
                    g_ctxh[fi] = h;
                    g_ctxl[fi] = __float2bfloat16(a0 - __bfloat162float(h));
                }
            }
            gridbar();
        }

        // ---- fused gates GEMM + pointwise (16 warps, 3-stage pipeline) ----
        {
            const __nv_bfloat16* embt_h = g_embh + (size_t)t * B_ * 512;
            const __nv_bfloat16* embt_l = g_embl + (size_t)t * B_ * 512;
            float accs[3][2][4];
#pragma unroll
            for (int p = 0; p < 3; p++)
#pragma unroll
                for (int n = 0; n < 2; n++)
#pragma unroll
                    for (int r = 0; r < 4; r++) accs[p][n][r] = 0.f;

#define GISSUE(c, s) do { \
        int k0 = (c) * 64; \
        int region = k0 >> 9; \
        int kb = k0 - (region << 9); \
        const __nv_bfloat16* srcH = (region == 0) ? embt_h : (region == 1) ? g_ctxh : g_hh; \
        const __nv_bfloat16* srcL = (region == 0) ? embt_l : (region == 1) ? g_ctxl : g_hl; \
        uint32_t st = sb + (uint32_t)((s) * 23040); \
        if (tid < 128) { \
            int sr = tid >> 3, q = tid & 7; \
            int gg_ = sr >> 2, rr_ = sr & 3; \
            size_t ga = (size_t)(gg_ * 512 + cta * 4 + rr_) * KC_ + k0 + q * 8; \
            CP16(st + sr * 144 + q * 16, g_Wc_hi + ga); \
        } else if (tid < 256) { \
            int t2 = tid - 128; int sr = t2 >> 3, q = t2 & 7; \
            int gg_ = sr >> 2, rr_ = sr & 3; \
            size_t ga = (size_t)(gg_ * 512 + cta * 4 + rr_) * KC_ + k0 + q * 8; \
            CP16(st + 2304 + sr * 144 + q * 16, g_Wc_lo + ga); \
        } else { \
            int base = (tid - 256) * 2; \
            _Pragma("unroll") \
            for (int uu = 0; uu < 2; ++uu) { \
                int u = base + uu; int row = u >> 3, q = u & 7; \
                CP16(st + 4608 + row * 144 + q * 16, srcH + (size_t)row * 512 + kb + q * 8); \
                CP16(st + 13824 + row * 144 + q * 16, srcL + (size_t)row * 512 + kb + q * 8); \
            } \
        } \
        CP_COMMIT(); \
    } while (0)

            GISSUE(0, 0);
            GISSUE(1, 1);
            for (int c = 0; c < 24; ++c) {
                if (c + 1 < 24) CP_WAIT(1); else CP_WAIT(0);
                __syncthreads();
                if (c + 2 < 24) GISSUE(c + 2, (c + 2) % 3);
                uint32_t st = sb + (uint32_t)((c % 3) * 23040);
                {
                    uint32_t ah[4], al[4], bh[2][2], bl[2][2];
                    LDMX4(ah[0], ah[1], ah[2], ah[3], st + aoffG + ksb);
                    LDMX4(al[0], al[1], al[2], al[3], st + 2304 + aoffG + ksb);
                    LDMX4(bh[0][0], bh[0][1], bh[1][0], bh[1][1],
                          st + 4608 + boffG + ksb);
                    LDMX4(bl[0][0], bl[0][1], bl[1][0], bl[1][1],
                          st + 13824 + boffG + ksb);
#pragma unroll
                    for (int ni = 0; ni < 2; ++ni) mma_bf16(accs[0][ni], ah, bh[ni]);
#pragma unroll
                    for (int ni = 0; ni < 2; ++ni) mma_bf16(accs[1][ni], ah, bl[ni]);
#pragma unroll
                    for (int ni = 0; ni < 2; ++ni) mma_bf16(accs[2][ni], al, bh[ni]);
                }
            }
#undef GISSUE
            __syncthreads();

            // store gate partials (four K-quarter buffers)
            float* gbuf = (float*)(smL + GB_OFF) + kq * 1024;  // [16][64]
            int g4 = lane >> 2, t4 = lane & 3;
#pragma unroll
            for (int ni = 0; ni < 2; ++ni) {
                int coln = ng * 16 + ni * 8 + 2 * t4;
                float c0 = accs[0][ni][0] + accs[1][ni][0] + accs[2][ni][0];
                float c1 = accs[0][ni][1] + accs[1][ni][1] + accs[2][ni][1];
                float c2 = accs[0][ni][2] + accs[1][ni][2] + accs[2][ni][2];
                float c3 = accs[0][ni][3] + accs[1][ni][3] + accs[2][ni][3];
                gbuf[g4 * 64 + coln]           = c0;
                gbuf[g4 * 64 + coln + 1]       = c1;
                gbuf[(g4 + 8) * 64 + coln]     = c2;
                gbuf[(g4 + 8) * 64 + coln + 1] = c3;
            }
            __syncthreads();

            // pointwise: tid<256 owns (h = cta*4 + r, batch bb)
            if (tid < 256) {
                float* gb = (float*)(smL + GB_OFF);
                int r = tid >> 6, bb = tid & 63;
                int h = cta * 4 + r;
                float gi = gb[r * 64 + bb] + gb[1024 + r * 64 + bb]
                         + gb[2048 + r * 64 + bb] + gb[3072 + r * 64 + bb]
                         + b_ih[h] + b_hh[h];
                float gf = gb[(4 + r) * 64 + bb] + gb[1024 + (4 + r) * 64 + bb]
                         + gb[2048 + (4 + r) * 64 + bb] + gb[3072 + (4 + r) * 64 + bb]
                         + b_ih[512 + h] + b_hh[512 + h];
                float gg = gb[(8 + r) * 64 + bb] + gb[1024 + (8 + r) * 64 + bb]
                         + gb[2048 + (8 + r) * 64 + bb] + gb[3072 + (8 + r) * 64 + bb]
                         + b_ih[1024 + h] + b_hh[1024 + h];
                float go = gb[(12 + r) * 64 + bb] + gb[1024 + (12 + r) * 64 + bb]
                         + gb[2048 + (12 + r) * 64 + bb] + gb[3072 + (12 + r) * 64 + bb]
                         + b_ih[1536 + h] + b_hh[1536 + h];
                float c  = g_c[(size_t)bb * 512 + h];
                float si = 1.f / (1.f + __expf(-gi));
                float sf = 1.f / (1.f + __expf(-gf));
                float so = 1.f / (1.f + __expf(-go));
                float eg = __expf(2.f * gg);
                float tg = 1.f - 2.f / (eg + 1.f);
                float c2 = sf * c + si * tg;
                float ec = __expf(2.f * c2);
                float tc = 1.f - 2.f / (ec + 1.f);
                float h2 = so * tc;
                g_c[(size_t)bb * 512 + h] = c2;
                g_h[(size_t)bb * 512 + h] = h2;
                __nv_bfloat16 hh = __float2bfloat16(h2);
                g_hh[(size_t)bb * 512 + h] = hh;
                g_hl[(size_t)bb * 512 + h] = __float2bfloat16(h2 - __bfloat162float(hh));
                size_t mrow = ((size_t)t * 64 + bb) * 512 + h;
                g_Hall_h[mrow] = __float2half_rn(h2);
            }
        }
        gridbar();
    }
}

// ---------------- launch ----------------------------------------------------
extern "C" void kernel_launch(void* const* d_in, const int* in_sizes, int n_in,
                              void* d_out, int out_size) {
    const float* enc  = (const float*)d_in[0];
    const int*   caps = (const int*)  d_in[1];
    const float* emb  = (const float*)d_in[2];
    const float* We   = (const float*)d_in[3];
    const float* be   = (const float*)d_in[4];
    const float* Wd   = (const float*)d_in[5];
    const float* bd   = (const float*)d_in[6];
    const float* vw   = (const float*)d_in[7];
    const float* vb   = (const float*)d_in[8];
    const float* W_ih = (const float*)d_in[9];
    const float* W_hh = (const float*)d_in[10];
    const float* b_ih = (const float*)d_in[11];
    const float* b_hh = (const float*)d_in[12];
    const float* Wf   = (const float*)d_in[13];
    const float* bf   = (const float*)d_in[14];
    float* out = (float*)d_out;

    cudaFuncSetAttribute(k_mma128, cudaFuncAttributeMaxDynamicSharedMemorySize, PIPE_SMEM_2P);
    cudaFuncSetAttribute(k_loop, cudaFuncAttributeMaxDynamicSharedMemorySize, LOOP_SMEM);

    void *p_enc_h, *p_We_h, *p_We_l, *p_Wf_h, *p_Hall_h, *p_encproj;
    cudaGetSymbolAddress(&p_enc_h, g_enc_h);
    cudaGetSymbolAddress(&p_We_h, g_We_h);
    cudaGetSymbolAddress(&p_We_l, g_We_l);
    cudaGetSymbolAddress(&p_Wf_h, g_Wf_h);
    cudaGetSymbolAddress(&p_Hall_h, g_Hall_h);
    cudaGetSymbolAddress(&p_encproj, g_encproj);

    k_init<<<(T_ * B_ * D_) / 256, 256>>>(caps, emb);
    k_ctx0<<<(B_ * F_) / 256, 256>>>(enc);
    k_prep<<<(int)(QALL / 256), 256>>>(enc, We, Wf, W_ih, W_hh);

    // enc_proj = enc @ We^T + be  (fp32 out, 2 passes, warp tile 64x64)
    k_mma128<<<dim3(M_ENC / 128, H_ / 128), 128, PIPE_SMEM_2P>>>(
        (const __half*)p_enc_h,
        (const __half*)p_We_h, (const __half*)p_We_l,
        be, (float*)p_encproj, F_, H_, 0, 1);

    // coalesced fp32 -> fp16 copy of encproj for the attention loop
    k_conv<<<(M_ENC * H_) / 4 / 256, 256>>>((const float*)p_encproj);

    // entire 32-step recurrence in one persistent kernel (512 threads/CTA)
    k_loop<<<GRID_P, 512, LOOP_SMEM>>>(enc, Wd, bd, vw, vb, b_ih, b_hh);

    // fc logits: Hall @ Wf^T + bf  (single fp16 pass, warp tile 64x64)
    k_mma128<<<dim3(M_FC / 128, V_ / 128), 128, PIPE_SMEM_1P>>>(
        (const __half*)p_Hall_h,
        (const __half*)p_Wf_h, (const __half*)p_Wf_h,
        bf, out, H_, V_, 1, 0);
}

// round 16
// speedup vs baseline: 1.1097x; 1.1097x over previous
#include <cuda_runtime.h>
#include <cuda_bf16.h>
#include <cuda_fp16.h>
#include <math.h>
#include <stdint.h>

// Problem constants
#define B_  64
#define L_  196
#define F_  512
#define T_  32
#define H_  512
#define D_  512
#define V_  32000
#define G4_ 2048
#define M_ENC (B_*L_)          // 12544
#define M_FC  (T_*B_)          // 2048
#define KC_ 1536               // D+F+H
#define GRID_P 128

// ====================== warp-mma helpers (sm_80 baseline ISA) ==============
__device__ __forceinline__ uint32_t smem_to_u32(const void* p) {
    uint32_t a;
    asm("{ .reg .u64 t; cvta.to.shared.u64 t, %1; cvt.u32.u64 %0, t; }" : "=r"(a) : "l"(p));
    return a;
}

#define LDMX4(r0,r1,r2,r3,addr) \
    asm volatile("ldmatrix.sync.aligned.m8n8.x4.shared.b16 {%0,%1,%2,%3}, [%4];" \
        : "=r"(r0),"=r"(r1),"=r"(r2),"=r"(r3) : "r"(addr))

#define CP16(dst, src) \
    asm volatile("cp.async.cg.shared.global [%0], [%1], 16;" :: "r"(dst), "l"(src))
#define CP_COMMIT() asm volatile("cp.async.commit_group;")
#define CP_WAIT(n)  asm volatile("cp.async.wait_group %0;" :: "n"(n))

__device__ __forceinline__ void mma_bf16(float* c, const uint32_t* a, const uint32_t* b) {
    asm volatile(
        "mma.sync.aligned.m16n8k16.row.col.f32.bf16.bf16.f32 "
        "{%0,%1,%2,%3}, {%4,%5,%6,%7}, {%8,%9}, {%0,%1,%2,%3};"
        : "+f"(c[0]), "+f"(c[1]), "+f"(c[2]), "+f"(c[3])
        : "r"(a[0]), "r"(a[1]), "r"(a[2]), "r"(a[3]), "r"(b[0]), "r"(b[1]));
}
__device__ __forceinline__ void mma_f16(float* c, const uint32_t* a, const uint32_t* b) {
    asm volatile(
        "mma.sync.aligned.m16n8k16.row.col.f32.f16.f16.f32 "
        "{%0,%1,%2,%3}, {%4,%5,%6,%7}, {%8,%9}, {%0,%1,%2,%3};"
        : "+f"(c[0]), "+f"(c[1]), "+f"(c[2]), "+f"(c[3])
        : "r"(a[0]), "r"(a[1]), "r"(a[2]), "r"(a[3]), "r"(b[0]), "r"(b[1]));
}

__device__ __forceinline__ float ftanh(float x) {
    float y;
    asm("tanh.approx.f32 %0, %1;" : "=f"(y) : "f"(x));
    return y;
}

// ---------------- scratch (static device globals; no allocations) ----------
__device__ float g_encproj[M_ENC * H_];
__device__ __half g_encproj_h[M_ENC * H_];
__device__ float g_h[B_ * H_];
__device__ float g_c[B_ * H_];
__device__ float g_dec[B_ * H_];
// bf16 operands (gates path)
__device__ __nv_bfloat16 g_embh[T_ * B_ * D_];
__device__ __nv_bfloat16 g_embl[T_ * B_ * D_];
__device__ __nv_bfloat16 g_ctxh[B_ * F_];
__device__ __nv_bfloat16 g_ctxl[B_ * F_];
__device__ __nv_bfloat16 g_hh[B_ * H_];
__device__ __nv_bfloat16 g_hl[B_ * H_];
__device__ __nv_bfloat16 g_Wc_hi[(size_t)G4_ * KC_];
__device__ __nv_bfloat16 g_Wc_lo[(size_t)G4_ * KC_];
// fp16 operands (big GEMMs)
__device__ __half g_enc_h[M_ENC * F_];
__device__ __half g_We_h[H_ * F_];
__device__ __half g_We_l[H_ * F_];
__device__ __half g_Wf_h[(size_t)V_ * H_];
__device__ __half g_Hall_h[M_FC * H_];
__device__ unsigned g_barArr = 0;

__device__ __forceinline__ void gridbar() {
    __syncthreads();
    if (threadIdx.x == 0) {
        unsigned my;
        asm volatile("atom.global.release.gpu.add.u32 %0, [%1], 1;"
                     : "=r"(my) : "l"(&g_barArr) : "memory");
        my += 1u;
        unsigned target = ((my + GRID_P - 1u) / GRID_P) * GRID_P;
        for (;;) {
            unsigned v;
            asm volatile("ld.global.acquire.gpu.u32 %0, [%1];"
                         : "=r"(v) : "l"(&g_barArr) : "memory");
            if (v >= target) break;
            __nanosleep(128);
        }
    }
    __syncthreads();
}

// ---------------- fused preamble splits (float4 vectorized) ----------------
#define Q0 ((size_t)(M_ENC * F_) / 4)         // enc  -> fp16 single
#define Q1 ((size_t)(H_ * F_) / 4)            // We   -> fp16 hi/lo
#define Q2 (((size_t)V_ * H_) / 4)            // Wf   -> fp16 single
#define Q3 (((size_t)G4_ * KC_) / 4)          // Wc   -> bf16 hi/lo
#define QALL (Q0 + Q1 + Q2 + Q3)

__device__ __forceinline__ void st_h4(__half* p, size_t off, float4 v) {
    __half2* q = (__half2*)(p + off);
    q[0] = __floats2half2_rn(v.x, v.y);
    q[1] = __floats2half2_rn(v.z, v.w);
}
__device__ __forceinline__ void st_h4_dual(__half* ph, __half* pl, size_t off, float4 v) {
    __half hx = __float2half_rn(v.x), hy = __float2half_rn(v.y);
    __half hz = __float2half_rn(v.z), hw = __float2half_rn(v.w);
    __half2* qh = (__half2*)(ph + off);
    qh[0] = __halves2half2(hx, hy); qh[1] = __halves2half2(hz, hw);
    __half2* ql = (__half2*)(pl + off);
    ql[0] = __floats2half2_rn(v.x - __half2float(hx), v.y - __half2float(hy));
    ql[1] = __floats2half2_rn(v.z - __half2float(hz), v.w - __half2float(hw));
}
__device__ __forceinline__ void st_b4_dual(__nv_bfloat16* ph, __nv_bfloat16* pl,
                                           size_t off, float4 v) {
    __nv_bfloat16 hx = __float2bfloat16(v.x), hy = __float2bfloat16(v.y);
    __nv_bfloat16 hz = __float2bfloat16(v.z), hw = __float2bfloat16(v.w);
    __nv_bfloat162* qh = (__nv_bfloat162*)(ph + off);
    qh[0] = __nv_bfloat162{hx, hy}; qh[1] = __nv_bfloat162{hz, hw};
    __nv_bfloat162* ql = (__nv_bfloat162*)(pl + off);
    ql[0] = __nv_bfloat162{__float2bfloat16(v.x - __bfloat162float(hx)),
                           __float2bfloat16(v.y - __bfloat162float(hy))};
    ql[1] = __nv_bfloat162{__float2bfloat16(v.z - __bfloat162float(hz)),
                           __float2bfloat16(v.w - __bfloat162float(hw))};
}

__global__ void k_prep(const float* __restrict__ enc, const float* __restrict__ We,
                       const float* __restrict__ Wf, const float* __restrict__ W_ih,
                       const float* __restrict__ W_hh) {
    size_t i4 = (size_t)blockIdx.x * 256 + threadIdx.x;   // exact grid
    if (i4 < Q0) {
        float4 v = ((const float4*)enc)[i4];
        st_h4(g_enc_h, i4 * 4, v);
    } else if (i4 < Q0 + Q1) {
        size_t o = i4 - Q0;
        float4 v = ((const float4*)We)[o];
        st_h4_dual(g_We_h, g_We_l, o * 4, v);
    } else if (i4 < Q0 + Q1 + Q2) {
        size_t o = i4 - Q0 - Q1;
        float4 v = ((const float4*)Wf)[o];
        st_h4(g_Wf_h, o * 4, v);
    } else {
        size_t o = i4 - Q0 - Q1 - Q2;
        size_t off = o * 4;
        int m = (int)(off / KC_), k = (int)(off % KC_);
        float4 v = (k < 1024)
            ? *(const float4*)(W_ih + (size_t)m * 1024 + k)
            : *(const float4*)(W_hh + (size_t)m * 512 + (k - 1024));
        st_b4_dual(g_Wc_hi, g_Wc_lo, off, v);
    }
}

// ---------------- convert encproj fp32 -> fp16 (coalesced) ------------------
__global__ void k_conv(const float* __restrict__ src) {
    size_t i4 = (size_t)blockIdx.x * 256 + threadIdx.x;   // over float4, exact
    float4 v = ((const float4*)src)[i4];
    st_h4(g_encproj_h, i4 * 4, v);
}

// ---------------- init: zero state, gather embeddings -> bf16 hi/lo --------
__global__ void k_init(const int* __restrict__ captions,
                       const float* __restrict__ embedding) {
    int idx = blockIdx.x * 256 + threadIdx.x;      // T*B*D exact
    if (idx < B_ * H_) {
        g_h[idx] = 0.f; g_c[idx] = 0.f;
        g_hh[idx] = __float2bfloat16(0.f);
        g_hl[idx] = __float2bfloat16(0.f);
    }
    int t   = idx >> 15;
    int rem = idx & 32767;
    int b   = rem >> 9;
    int d   = rem & 511;
    int cap = captions[b * T_ + t];
    float x = embedding[(size_t)cap * D_ + d];
    __nv_bfloat16 h = __float2bfloat16(x);
    g_embh[idx] = h;
    g_embl[idx] = __float2bfloat16(x - __bfloat162float(h));
}

// ---------------- ctx0 = mean over L -> bf16 hi/lo -------------------------
__global__ void k_ctx0(const float* __restrict__ enc) {
    int idx = blockIdx.x * 256 + threadIdx.x;      // B*F exact
    int b = idx >> 9, f = idx & 511;
    const float* p = enc + ((size_t)b * L_) * F_ + f;
    float s = 0.f;
    for (int l = 0; l < L_; ++l) s += p[(size_t)l * F_];
    s *= (1.0f / (float)L_);
    __nv_bfloat16 h = __float2bfloat16(s);
    g_ctxh[idx] = h;
    g_ctxl[idx] = __float2bfloat16(s - __bfloat162float(h));
}

// ---------------- big GEMM (tile 128x128), fp16, 3-stage pipeline ----------
#define T32  (128 * 40)
#define T32B (T32 * 2)                  // 10240 bytes per tile
#define PIPE_SMEM_2P (3 * 3 * T32B)     // two-pass: 3 stages x 3 tiles = 92160
#define PIPE_SMEM_1P (3 * 2 * T32B)     // one-pass: 3 stages x 2 tiles = 61440

__global__ __launch_bounds__(256, 2) void k_mma128(
    const __half* __restrict__ A,
    const __half* __restrict__ Bhi, const __half* __restrict__ Blo,
    const float* __restrict__ bias, float* __restrict__ out,
    int K, int ldc, int fc_remap, int two_pass)
{
    extern __shared__ char smem[];
    uint32_t sb = smem_to_u32(smem);
    int tid = threadIdx.x, wid = tid >> 5, lane = tid & 31;
    int m0 = blockIdx.x * 128, n0 = blockIdx.y * 128;
    int warp_m = wid & 1, warp_n = wid >> 1;
    uint32_t stg = (uint32_t)((two_pass ? 3 : 2) * T32B);

    float acc[4][4][4];
#pragma unroll
    for (int i = 0; i < 4; i++)
#pragma unroll
        for (int j = 0; j < 4; j++)
#pragma unroll
            for (int r = 0; r < 4; r++) acc[i][j][r] = 0.f;

    int row_ld = tid >> 1, q_ld = tid & 1;
    uint32_t so_ld = (uint32_t)(row_ld * 80 + q_ld * 32);
    int sub = lane >> 3, ri = lane & 7;
    uint32_t aoff = (uint32_t)((((sub & 1) * 8 + ri) * 40 + (sub >> 1) * 8) * 2)
                  + (uint32_t)(warp_m * 64 * 80);
    uint32_t boff = (uint32_t)((((sub >> 1) * 8 + ri) * 40 + (sub & 1) * 8) * 2)
                  + (uint32_t)(warp_n * 32 * 80);

    int NC = K >> 5;

#define ISSUE(c, s) do { \
        int k0 = (c) << 5; \
        uint32_t st = sb + (uint32_t)(s) * stg; \
        size_t gA = (size_t)(m0 + row_ld) * K + k0 + q_ld * 16; \
        size_t gB = (size_t)(n0 + row_ld) * K + k0 + q_ld * 16; \
        CP16(st + so_ld,      A + gA); \
        CP16(st + so_ld + 16, A + gA + 8); \
        CP16(st + 1 * T32B + so_ld,      Bhi + gB); \
        CP16(st + 1 * T32B + so_ld + 16, Bhi + gB + 8); \
        if (two_pass) { \
            CP16(st + 2 * T32B + so_ld,      Blo + gB); \
            CP16(st + 2 * T32B + so_ld + 16, Blo + gB + 8); \
        } \
        CP_COMMIT(); \
    } while (0)

    ISSUE(0, 0);
    ISSUE(1, 1);
    for (int c = 0; c < NC; ++c) {
        if (c + 1 < NC) CP_WAIT(1); else CP_WAIT(0);
        __syncthreads();
        if (c + 2 < NC) ISSUE(c + 2, (c + 2) % 3);
        int s = c % 3;
        uint32_t bA  = sb + (uint32_t)s * stg + aoff;
        uint32_t bBh = sb + (uint32_t)s * stg + 1 * T32B + boff;
        uint32_t bBl = sb + (uint32_t)s * stg + 2 * T32B + boff;
#pragma unroll
        for (int ks = 0; ks < 32; ks += 16) {
            uint32_t ah[4][4], bh[4][2], bl[4][2];
#pragma unroll
            for (int mi = 0; mi < 4; ++mi)
                LDMX4(ah[mi][0], ah[mi][1], ah[mi][2], ah[mi][3],
                      bA + (uint32_t)(mi * 16 * 80 + ks * 2));
            LDMX4(bh[0][0], bh[0][1], bh[1][0], bh[1][1], bBh + (uint32_t)(ks * 2));
            LDMX4(bh[2][0], bh[2][1], bh[3][0], bh[3][1], bBh + (uint32_t)(16 * 80 + ks * 2));
#pragma unroll
            for (int mi = 0; mi < 4; ++mi)
#pragma unroll
                for (int ni = 0; ni < 4; ++ni)
                    mma_f16(acc[mi][ni], ah[mi], bh[ni]);
            if (two_pass) {
                LDMX4(bl[0][0], bl[0][1], bl[1][0], bl[1][1], bBl + (uint32_t)(ks * 2));
                LDMX4(bl[2][0], bl[2][1], bl[3][0], bl[3][1], bBl + (uint32_t)(16 * 80 + ks * 2));
#pragma unroll
                for (int mi = 0; mi < 4; ++mi)
#pragma unroll
                    for (int ni = 0; ni < 4; ++ni)
                        mma_f16(acc[mi][ni], ah[mi], bl[ni]);
            }
        }
    }
#undef ISSUE

    int g = lane >> 2, t4 = lane & 3;
    float2 bv[4];
#pragma unroll
    for (int ni = 0; ni < 4; ++ni)
        bv[ni] = *(const float2*)(bias + n0 + warp_n * 32 + ni * 8 + 2 * t4);
#pragma unroll
    for (int mi = 0; mi < 4; ++mi)
#pragma unroll
        for (int rr = 0; rr < 2; ++rr) {
            int m = m0 + warp_m * 64 + mi * 16 + rr * 8 + g;
            int row = fc_remap ? ((m & 63) * T_ + (m >> 6)) : m;
            float* po = out + (size_t)row * ldc + n0 + warp_n * 32 + 2 * t4;
#pragma unroll
            for (int ni = 0; ni < 4; ++ni) {
                float2 v;
                v.x = acc[mi][ni][rr * 2 + 0] + bv[ni].x;
                v.y = acc[mi][ni][rr * 2 + 1] + bv[ni].y;
                *(float2*)(po + ni * 8) = v;
            }
        }
}

// ---------------- persistent fused recurrence kernel (512 threads) ---------
// dyn smem layout (bytes):
//   gates: stage s at s*23040 (3 stages = 69120); gatebuf @69120 (16384)
//          -> 85504 max
//   dec:   hs[64][260]@0 (66560), ws[4][256]@66560 (4096), pr[512]@70656 (2048)
//   attn:  dec_s[512]@0, vw_s[512]@2048, sc[200]@4096, sred[256]@5120,
//          red2[16][256]@6144 (16384) -> 22528
#define GB_OFF 69120
#define LOOP_SMEM 85504

__global__ __launch_bounds__(512, 1) void k_loop(
    const float* __restrict__ enc, const float* __restrict__ Wd,
    const float* __restrict__ bd, const float* __restrict__ vw,
    const float* __restrict__ vb, const float* __restrict__ b_ih,
    const float* __restrict__ b_hh)
{
    extern __shared__ char smL[];
    uint32_t sb = smem_to_u32(smL);
    int cta = blockIdx.x;
    int tid = threadIdx.x, wid = tid >> 5, lane = tid & 31;
    int sub = lane >> 3, ri = lane & 7;

    // fused-gates constants: 16 warps = kq(4 K-quarters) x ng(4 batch groups)
    int kq = wid >> 2, ng = wid & 3;
    uint32_t aoffG = (uint32_t)((((sub & 1) * 8 + ri) * 72 + (sub >> 1) * 8) * 2);
    uint32_t boffG = (uint32_t)((((sub >> 1) * 8 + ri) * 72 + (sub & 1) * 8) * 2)
                   + (uint32_t)(ng * 16 * 144);
    uint32_t ksb = (uint32_t)(kq * 32);            // byte offset of this warp's 16-col slice

    for (int t = 0; t < T_; ++t) {
        if (t > 0) {
            // ---- dec: cta computes dec[:, cta*4 .. +3]; 2 big K-chunks ----
            {
                float* hs = (float*)smL;                // [64][260]
                float* ws = (float*)(smL + 66560);      // [4][256]
                float* pr = (float*)(smL + 70656);      // [512]
                int n0 = cta * 4;
                int bq = tid & 63, jj = (tid >> 6) & 3, kh = tid >> 8;
                float acc = 0.f;
                for (int kb = 0; kb < 512; kb += 256) {
#pragma unroll
                    for (int it = 0; it < 8; ++it) {
                        int u = tid + it * 512;         // 0..4095 float4 slots
                        int r = u >> 6, kk = (u & 63) * 4;
                        float4 v = *(const float4*)(g_h + (size_t)r * 512 + kb + kk);
                        *(float4*)&hs[r * 260 + kk] = v;
                    }
                    if (tid < 256) {
                        int n = tid >> 6, kk = (tid & 63) * 4;
                        float4 v = *(const float4*)(Wd + (size_t)(n0 + n) * 512 + kb + kk);
                        *(float4*)&ws[n * 256 + kk] = v;
                    }
                    __syncthreads();
                    const float4* hv = (const float4*)&hs[bq * 260 + kh * 128];
                    const float4* wv = (const float4*)&ws[jj * 256 + kh * 128];
#pragma unroll
                    for (int k4 = 0; k4 < 32; ++k4) {
                        float4 a = hv[k4], b = wv[k4];
                        acc += a.x * b.x + a.y * b.y + a.z * b.z + a.w * b.w;
                    }
                    __syncthreads();
                }
                pr[tid] = acc;
                __syncthreads();
                if (tid < 256)
                    g_dec[(size_t)bq * 512 + n0 + jj] = pr[tid] + pr[tid + 256] + bd[n0 + jj];
            }
            gridbar();

            // ---- merged attention: b = cta>>1, f-half = cta&1 ----
            {
                float* dec_s = (float*)smL;             // [512]
                float* vw_s  = (float*)(smL + 2048);    // [512]
                float* sc    = (float*)(smL + 4096);    // [200]
                float* sred  = (float*)(smL + 5120);    // [256]
                float* red2  = (float*)(smL + 6144);    // [16][256]
                int b = cta >> 1, f0 = (cta & 1) * 256;
                dec_s[tid] = g_dec[(size_t)b * 512 + tid];
                vw_s[tid]  = vw[tid];
                __syncthreads();
                const float2* dec2 = (const float2*)dec_s;
                const float2* vw2  = (const float2*)vw_s;
                float v_b = vb[0];
                for (int l = wid; l < L_; l += 16) {
                    const __half2* ep2 = (const __half2*)(g_encproj_h + ((size_t)(b * L_ + l)) * 512);
                    float s = 0.f;
#pragma unroll
                    for (int j = 0; j < 8; ++j) {
                        int idx = lane + 32 * j;
                        float2 e = __half22float2(ep2[idx]);
                        float2 dd = dec2[idx];
                        float2 vv = vw2[idx];
                        s += ftanh(e.x + dd.x) * vv.x + ftanh(e.y + dd.y) * vv.y;
                    }
#pragma unroll
                    for (int off = 16; off; off >>= 1) s += __shfl_xor_sync(0xffffffffu, s, off);
                    if (lane == 0) sc[l] = s + v_b;
                }
                __syncthreads();
                if (tid < 256) {
                    float mv = (tid < L_) ? sc[tid] : -1e30f;
                    sred[tid] = mv;
                }
                __syncthreads();
                for (int s = 128; s; s >>= 1) {
                    if (tid < s) sred[tid] = fmaxf(sred[tid], sred[tid + s]);
                    __syncthreads();
                }
                float mx = sred[0]; __syncthreads();
                float ev = 0.f;
                if (tid < 256) {
                    ev = (tid < L_) ? __expf(sc[tid] - mx) : 0.f;
                    sred[tid] = ev;
                }
                __syncthreads();
                for (int s = 128; s; s >>= 1) {
                    if (tid < s) sred[tid] += sred[tid + s];
                    __syncthreads();
                }
                float inv = 1.0f / sred[0]; __syncthreads();
                if (tid < L_) sc[tid] = ev * inv;
                __syncthreads();
                float2 a2[4];
#pragma unroll
                for (int j = 0; j < 4; ++j) a2[j] = float2{0.f, 0.f};
                for (int l = wid; l < L_; l += 16) {
                    float s = sc[l];
                    const __half2* e2 = (const __half2*)(g_enc_h + ((size_t)(b * L_ + l)) * 512 + f0);
#pragma unroll
                    for (int j = 0; j < 4; ++j) {
                        float2 e = __half22float2(e2[lane + 32 * j]);
                        a2[j].x += s * e.x; a2[j].y += s * e.y;
                    }
                }
#pragma unroll
                for (int j = 0; j < 4; ++j)
                    ((float2*)(red2 + wid * 256))[lane + 32 * j] = a2[j];
                __syncthreads();
                if (tid < 256) {
                    float a0 = 0.f;
#pragma unroll
                    for (int w = 0; w < 16; w++) a0 += red2[w * 256 + tid];
                    int fi = b * 512 + f0 + tid;
                    __nv_bfloat16 h = __float2bfloat16(a0);
                    g_ctxh[fi] = h;
                    g_ctxl[fi] = __float2bfloat16(a0 - __bfloat162float(h));
                }
            }
            gridbar();
        }

        // ---- fused gates GEMM + pointwise (16 warps, 3-stage pipeline) ----
        {
            const __nv_bfloat16* embt_h = g_embh + (size_t)t * B_ * 512;
            const __nv_bfloat16* embt_l = g_embl + (size_t)t * B_ * 512;
            float accs[3][2][4];
#pragma unroll
            for (int p = 0; p < 3; p++)
#pragma unroll
                for (int n = 0; n < 2; n++)
#pragma unroll
                    for (int r = 0; r < 4; r++) accs[p][n][r] = 0.f;

#define GISSUE(c, s) do { \
        int k0 = (c) * 64; \
        int region = k0 >> 9; \
        int kb = k0 - (region << 9); \
        const __nv_bfloat16* srcH = (region == 0) ? embt_h : (region == 1) ? g_ctxh : g_hh; \
        const __nv_bfloat16* srcL = (region == 0) ? embt_l : (region == 1) ? g_ctxl : g_hl; \
        uint32_t st = sb + (uint32_t)((s) * 23040); \
        if (tid < 128) { \
            int sr = tid >> 3, q = tid & 7; \
            int gg_ = sr >> 2, rr_ = sr & 3; \
            size_t ga = (size_t)(gg_ * 512 + cta * 4 + rr_) * KC_ + k0 + q * 8; \
            CP16(st + sr * 144 + q * 16, g_Wc_hi + ga); \
        } else if (tid < 256) { \
            int t2 = tid - 128; int sr = t2 >> 3, q = t2 & 7; \
            int gg_ = sr >> 2, rr_ = sr & 3; \
            size_t ga = (size_t)(gg_ * 512 + cta * 4 + rr_) * KC_ + k0 + q * 8; \
            CP16(st + 2304 + sr * 144 + q * 16, g_Wc_lo + ga); \
        } else { \
            int base = (tid - 256) * 2; \
            _Pragma("unroll") \
            for (int uu = 0; uu < 2; ++uu) { \
                int u = base + uu; int row = u >> 3, q = u & 7; \
                CP16(st + 4608 + row * 144 + q * 16, srcH + (size_t)row * 512 + kb + q * 8); \
                CP16(st + 13824 + row * 144 + q * 16, srcL + (size_t)row * 512 + kb + q * 8); \
            } \
        } \
        CP_COMMIT(); \
    } while (0)

            GISSUE(0, 0);
            GISSUE(1, 1);
            for (int c = 0; c < 24; ++c) {
                if (c + 1 < 24) CP_WAIT(1); else CP_WAIT(0);
                __syncthreads();
                if (c + 2 < 24) GISSUE(c + 2, (c + 2) % 3);
                uint32_t st = sb + (uint32_t)((c % 3) * 23040);
                {
                    uint32_t ah[4], al[4], bh[2][2], bl[2][2];
                    LDMX4(ah[0], ah[1], ah[2], ah[3], st + aoffG + ksb);
                    LDMX4(al[0], al[1], al[2], al[3], st + 2304 + aoffG + ksb);
                    LDMX4(bh[0][0], bh[0][1], bh[1][0], bh[1][1],
                          st + 4608 + boffG + ksb);
                    LDMX4(bl[0][0], bl[0][1], bl[1][0], bl[1][1],
                          st + 13824 + boffG + ksb);
#pragma unroll
                    for (int ni = 0; ni < 2; ++ni) mma_bf16(accs[0][ni], ah, bh[ni]);
#pragma unroll
                    for (int ni = 0; ni < 2; ++ni) mma_bf16(accs[1][ni], ah, bl[ni]);
#pragma unroll
                    for (int ni = 0; ni < 2; ++ni) mma_bf16(accs[2][ni], al, bh[ni]);
                }
            }
#undef GISSUE
            __syncthreads();

            // store gate partials (four K-quarter buffers)
            float* gbuf = (float*)(smL + GB_OFF) + kq * 1024;  // [16][64]
            int g4 = lane >> 2, t4 = lane & 3;
#pragma unroll
            for (int ni = 0; ni < 2; ++ni) {
                int coln = ng * 16 + ni * 8 + 2 * t4;
                float c0 = accs[0][ni][0] + accs[1][ni][0] + accs[2][ni][0];
                float c1 = accs[0][ni][1] + accs[1][ni][1] + accs[2][ni][1];
                float c2 = accs[0][ni][2] + accs[1][ni][2] + accs[2][ni][2];
                float c3 = accs[0][ni][3] + accs[1][ni][3] + accs[2][ni][3];
                gbuf[g4 * 64 + coln]           = c0;
                gbuf[g4 * 64 + coln + 1]       = c1;
                gbuf[(g4 + 8) * 64 + coln]     = c2;
                gbuf[(g4 + 8) * 64 + coln + 1] = c3;
            }
            __syncthreads();

            // pointwise: tid<256 owns (h = cta*4 + r, batch bb)
            if (tid < 256) {
                float* gb = (float*)(smL + GB_OFF);
                int r = tid >> 6, bb = tid & 63;
                int h = cta * 4 + r;
                float gi = gb[r * 64 + bb] + gb[1024 + r * 64 + bb]
                         + gb[2048 + r * 64 + bb] + gb[3072 + r * 64 + bb]
                         + b_ih[h] + b_hh[h];
                float gf = gb[(4 + r) * 64 + bb] + gb[1024 + (4 + r) * 64 + bb]
                         + gb[2048 + (4 + r) * 64 + bb] + gb[3072 + (4 + r) * 64 + bb]
                         + b_ih[512 + h] + b_hh[512 + h];
                float gg = gb[(8 + r) * 64 + bb] + gb[1024 + (8 + r) * 64 + bb]
                         + gb[2048 + (8 + r) * 64 + bb] + gb[3072 + (8 + r) * 64 + bb]
                         + b_ih[1024 + h] + b_hh[1024 + h];
                float go = gb[(12 + r) * 64 + bb] + gb[1024 + (12 + r) * 64 + bb]
                         + gb[2048 + (12 + r) * 64 + bb] + gb[3072 + (12 + r) * 64 + bb]
                         + b_ih[1536 + h] + b_hh[1536 + h];
                float c  = g_c[(size_t)bb * 512 + h];
                float si = 1.f / (1.f + __expf(-gi));
                float sf = 1.f / (1.f + __expf(-gf));
                float so = 1.f / (1.f + __expf(-go));
                float eg = __expf(2.f * gg);
                float tg = 1.f - 2.f / (eg + 1.f);
                float c2 = sf * c + si * tg;
                float ec = __expf(2.f * c2);
                float tc = 1.f - 2.f / (ec + 1.f);
                float h2 = so * tc;
                g_c[(size_t)bb * 512 + h] = c2;
                g_h[(size_t)bb * 512 + h] = h2;
                __nv_bfloat16 hh = __float2bfloat16(h2);
                g_hh[(size_t)bb * 512 + h] = hh;
                g_hl[(size_t)bb * 512 + h] = __float2bfloat16(h2 - __bfloat162float(hh));
                size_t mrow = ((size_t)t * 64 + bb) * 512 + h;
                g_Hall_h[mrow] = __float2half_rn(h2);
            }
        }
        gridbar();
    }
}

// ---------------- launch ----------------------------------------------------
extern "C" void kernel_launch(void* const* d_in, const int* in_sizes, int n_in,
                              void* d_out, int out_size) {
    const float* enc  = (const float*)d_in[0];
    const int*   caps = (const int*)  d_in[1];
    const float* emb  = (const float*)d_in[2];
    const float* We   = (const float*)d_in[3];
    const float* be   = (const float*)d_in[4];
    const float* Wd   = (const float*)d_in[5];
    const float* bd   = (const float*)d_in[6];
    const float* vw   = (const float*)d_in[7];
    const float* vb   = (const float*)d_in[8];
    const float* W_ih = (const float*)d_in[9];
    const float* W_hh = (const float*)d_in[10];
    const float* b_ih = (const float*)d_in[11];
    const float* b_hh = (const float*)d_in[12];
    const float* Wf   = (const float*)d_in[13];
    const float* bf   = (const float*)d_in[14];
    float* out = (float*)d_out;

    cudaFuncSetAttribute(k_mma128, cudaFuncAttributeMaxDynamicSharedMemorySize, PIPE_SMEM_2P);
    cudaFuncSetAttribute(k_loop, cudaFuncAttributeMaxDynamicSharedMemorySize, LOOP_SMEM);

    void *p_enc_h, *p_We_h, *p_We_l, *p_Wf_h, *p_Hall_h, *p_encproj;
    cudaGetSymbolAddress(&p_enc_h, g_enc_h);
    cudaGetSymbolAddress(&p_We_h, g_We_h);
    cudaGetSymbolAddress(&p_We_l, g_We_l);
    cudaGetSymbolAddress(&p_Wf_h, g_Wf_h);
    cudaGetSymbolAddress(&p_Hall_h, g_Hall_h);
    cudaGetSymbolAddress(&p_encproj, g_encproj);

    k_init<<<(T_ * B_ * D_) / 256, 256>>>(caps, emb);
    k_ctx0<<<(B_ * F_) / 256, 256>>>(enc);
    k_prep<<<(int)(QALL / 256), 256>>>(enc, We, Wf, W_ih, W_hh);

    // enc_proj = enc @ We^T + be  (fp32 out, 2 passes, 3-stage)
    k_mma128<<<dim3(M_ENC / 128, H_ / 128), 256, PIPE_SMEM_2P>>>(
        (const __half*)p_enc_h,
        (const __half*)p_We_h, (const __half*)p_We_l,
        be, (float*)p_encproj, F_, H_, 0, 1);

    // coalesced fp32 -> fp16 copy of encproj for the attention loop
    k_conv<<<(M_ENC * H_) / 4 / 256, 256>>>((const float*)p_encproj);

    // entire 32-step recurrence in one persistent kernel (512 threads/CTA)
    k_loop<<<GRID_P, 512, LOOP_SMEM>>>(enc, Wd, bd, vw, vb, b_ih, b_hh);

    // fc logits: Hall @ Wf^T + bf  (single fp16 pass, 3-stage)
    k_mma128<<<dim3(M_FC / 128, V_ / 128), 256, PIPE_SMEM_1P>>>(
        (const __half*)p_Hall_h,
        (const __half*)p_Wf_h, (const __half*)p_Wf_h,
        bf, out, H_, V_, 1, 0);
}